// round 3
// baseline (speedup 1.0000x reference)
#include <cuda_runtime.h>
#include <math.h>

#define B    64
#define H    1024
#define NH   8
#define HD   128
#define SQ   24
#define NE   512
#define K3H  3072
#define H4   4096

#define LOGITS_TOT (SQ*B*NE)   // 786432
#define IDX_TOT    (SQ*B*3)    // 4608

#define KS_QKV   4

// ---------------- persistent device scratch (no allocations allowed) ----------------
__device__ float d_Wcat[(size_t)H4 * H4];   // gate-interleaved: row' = 4*j+g
__device__ float d_bcat[H4];                // interleaved combined bias
__device__ float d_X[(size_t)B * K3H];      // x part (top3 gather output)
__device__ float d_hbuf[2][(size_t)B * H];  // ping-pong hidden
__device__ float d_c[(size_t)B * H];
__device__ float d_qkvp[KS_QKV * (size_t)B * K3H];
__device__ float d_q[(size_t)B * H];
__device__ float d_Kc[(size_t)SQ * B * H];
__device__ float d_Vc[(size_t)SQ * B * H];
__device__ float d_ctx[(size_t)B * H];
__device__ float d_qin[(size_t)B * H];
__device__ float d_qf[(size_t)B * H];

// ---------------- init ----------------
__global__ void init_wcat(const float* __restrict__ W_ih, const float* __restrict__ W_hh) {
    size_t id = (size_t)blockIdx.x * 256 + threadIdx.x;   // H4*H4 elems
    int r = (int)(id >> 12);          // interleaved dest row
    int k = (int)(id & 4095);
    int g = r & 3, j = r >> 2;
    int src = g * H + j;              // original row g*1024+j
    d_Wcat[id] = (k < K3H) ? W_ih[(size_t)src * K3H + k]
                           : W_hh[(size_t)src * H + (k - K3H)];
}

__global__ void init_state(const float* __restrict__ hidden,
                           const float* __restrict__ cell,
                           const float* __restrict__ init_in,
                           const float* __restrict__ b_ih,
                           const float* __restrict__ b_hh) {
    int id = blockIdx.x * 256 + threadIdx.x;              // B*H4 = 262144
    int b = id >> 12;
    int k = id & 4095;
    if (k < K3H) {
        d_X[(size_t)b * K3H + k] = init_in[(size_t)b * K3H + k];
    } else {
        int j = k - K3H;
        d_hbuf[0][(size_t)b * H + j] = hidden[(size_t)b * H + j];
        d_c[(size_t)b * H + j] = cell[(size_t)b * H + j];
    }
    if (id < H4) {  // interleaved bias: bcat[4j+g] = b_ih[g*1024+j]+b_hh[g*1024+j]
        int g = id & 3, j = id >> 2;
        d_bcat[id] = b_ih[g * H + j] + b_hh[g * H + j];
    }
}

// ---------------- gates GEMM + fused LSTM epilogue ----------------
// Tile 64x32, full K=4096 (A = [X | h_in] virtually concatenated), 128 blocks.
// Output cols (gate-interleaved) n0+tc*4+{0..3} = gates i,f,g,o of j=(n0>>2)+tc.
__global__ __launch_bounds__(256)
void gates_lstm(const float* __restrict__ hin, float* __restrict__ hout)
{
    __shared__ __align__(16) float As[2][16][68];
    __shared__ __align__(16) float Ws[2][16][36];

    const int tx = threadIdx.x;
    const int tr = tx >> 3;        // 0..31 -> rows tr*2, tr*2+1
    const int tc = tx & 7;         // 0..7  -> cols tc*4..+3
    const int n0 = blockIdx.x * 32;

    const int aRow = tx & 63, aCg = tx >> 6;   // A: 64 rows x 4 k-groups of 4
    const int wRow = tx >> 2, wCg = tx & 3;    // W: 32 rows x 4 k-groups (tx<128)
    const bool wAct = (tx < 128);

    const float* Xrow = d_X + (size_t)aRow * K3H;
    const float* Hrow = hin + (size_t)aRow * H;
    const float* Wptr = d_Wcat + (size_t)(n0 + wRow) * H4 + wCg * 4;

    float acc[2][4];
#pragma unroll
    for (int i = 0; i < 2; i++)
#pragma unroll
        for (int j = 0; j < 4; j++) acc[i][j] = 0.f;

    // prologue
    {
        int k = aCg * 4;
        float4 va = *reinterpret_cast<const float4*>(Xrow + k);
        As[0][aCg * 4 + 0][aRow] = va.x; As[0][aCg * 4 + 1][aRow] = va.y;
        As[0][aCg * 4 + 2][aRow] = va.z; As[0][aCg * 4 + 3][aRow] = va.w;
        if (wAct) {
            float4 vw = *reinterpret_cast<const float4*>(Wptr);
            Ws[0][wCg * 4 + 0][wRow] = vw.x; Ws[0][wCg * 4 + 1][wRow] = vw.y;
            Ws[0][wCg * 4 + 2][wRow] = vw.z; Ws[0][wCg * 4 + 3][wRow] = vw.w;
        }
    }
    __syncthreads();

    const int nk = H4 / 16;   // 256
    for (int it = 0; it < nk; it++) {
        const int st = it & 1;
        float4 va, vw;
        if (it + 1 < nk) {
            int k = (it + 1) * 16 + aCg * 4;
            va = (k < K3H) ? *reinterpret_cast<const float4*>(Xrow + k)
                           : *reinterpret_cast<const float4*>(Hrow + (k - K3H));
            if (wAct) vw = *reinterpret_cast<const float4*>(Wptr + (it + 1) * 16);
        }
#pragma unroll
        for (int kk = 0; kk < 16; kk++) {
            float2 a2 = *reinterpret_cast<const float2*>(&As[st][kk][tr * 2]);
            float4 b4 = *reinterpret_cast<const float4*>(&Ws[st][kk][tc * 4]);
            acc[0][0] = fmaf(a2.x, b4.x, acc[0][0]);
            acc[0][1] = fmaf(a2.x, b4.y, acc[0][1]);
            acc[0][2] = fmaf(a2.x, b4.z, acc[0][2]);
            acc[0][3] = fmaf(a2.x, b4.w, acc[0][3]);
            acc[1][0] = fmaf(a2.y, b4.x, acc[1][0]);
            acc[1][1] = fmaf(a2.y, b4.y, acc[1][1]);
            acc[1][2] = fmaf(a2.y, b4.z, acc[1][2]);
            acc[1][3] = fmaf(a2.y, b4.w, acc[1][3]);
        }
        if (it + 1 < nk) {
            const int sn = st ^ 1;
            As[sn][aCg * 4 + 0][aRow] = va.x; As[sn][aCg * 4 + 1][aRow] = va.y;
            As[sn][aCg * 4 + 2][aRow] = va.z; As[sn][aCg * 4 + 3][aRow] = va.w;
            if (wAct) {
                Ws[sn][wCg * 4 + 0][wRow] = vw.x; Ws[sn][wCg * 4 + 1][wRow] = vw.y;
                Ws[sn][wCg * 4 + 2][wRow] = vw.z; Ws[sn][wCg * 4 + 3][wRow] = vw.w;
            }
        }
        __syncthreads();
    }

    // fused LSTM epilogue: this thread owns gates (i,f,g,o) of j for rows tr*2,tr*2+1
    const int j = (n0 >> 2) + tc;
    float4 bc = *reinterpret_cast<const float4*>(&d_bcat[n0 + tc * 4]);
#pragma unroll
    for (int i = 0; i < 2; i++) {
        int b = tr * 2 + i;
        float gi = acc[i][0] + bc.x;
        float gf = acc[i][1] + bc.y;
        float gg = acc[i][2] + bc.z;
        float go = acc[i][3] + bc.w;
        float si = 1.f / (1.f + expf(-gi));
        float sf = 1.f / (1.f + expf(-gf));
        float so = 1.f / (1.f + expf(-go));
        float c = sf * d_c[(size_t)b * H + j] + si * tanhf(gg);
        d_c[(size_t)b * H + j] = c;
        hout[(size_t)b * H + j] = so * tanhf(c);
    }
}

// ---------------- generic K-split GEMM (for QKV): C_part = A[64,ks] * W[N,ks]^T ----------------
__global__ __launch_bounds__(256)
void gemm64(const float* __restrict__ A, int lda,
            const float* __restrict__ W, int K, int N,
            float* __restrict__ C, int kper)
{
    __shared__ __align__(16) float As[2][16][68];
    __shared__ __align__(16) float Ws[2][16][68];

    const int tx = threadIdx.x;
    const int tr = tx >> 4;
    const int tc = tx & 15;
    const int nblk = blockIdx.x * 64;
    const int k0 = blockIdx.y * kper;

    const int aRow = tx & 63, aCg = tx >> 6;
    const int wRow = tx >> 2, wCg = tx & 3;

    const float* Aptr = A + (size_t)aRow * lda + k0 + aCg * 4;
    const float* Wptr = W + (size_t)(nblk + wRow) * K + k0 + wCg * 4;

    float acc[4][4];
#pragma unroll
    for (int i = 0; i < 4; i++)
#pragma unroll
        for (int j = 0; j < 4; j++) acc[i][j] = 0.f;

    const int nk = kper / 16;
    {
        float4 va = *reinterpret_cast<const float4*>(Aptr);
        float4 vw = *reinterpret_cast<const float4*>(Wptr);
        As[0][aCg * 4 + 0][aRow] = va.x; As[0][aCg * 4 + 1][aRow] = va.y;
        As[0][aCg * 4 + 2][aRow] = va.z; As[0][aCg * 4 + 3][aRow] = va.w;
        Ws[0][wCg * 4 + 0][wRow] = vw.x; Ws[0][wCg * 4 + 1][wRow] = vw.y;
        Ws[0][wCg * 4 + 2][wRow] = vw.z; Ws[0][wCg * 4 + 3][wRow] = vw.w;
    }
    __syncthreads();

    for (int it = 0; it < nk; it++) {
        const int st = it & 1;
        float4 va, vw;
        if (it + 1 < nk) {
            va = *reinterpret_cast<const float4*>(Aptr + (it + 1) * 16);
            vw = *reinterpret_cast<const float4*>(Wptr + (it + 1) * 16);
        }
#pragma unroll
        for (int kk = 0; kk < 16; kk++) {
            float4 a4 = *reinterpret_cast<const float4*>(&As[st][kk][tr * 4]);
            float4 b4 = *reinterpret_cast<const float4*>(&Ws[st][kk][tc * 4]);
            float a[4] = {a4.x, a4.y, a4.z, a4.w};
            float bb[4] = {b4.x, b4.y, b4.z, b4.w};
#pragma unroll
            for (int i = 0; i < 4; i++)
#pragma unroll
                for (int jj = 0; jj < 4; jj++)
                    acc[i][jj] = fmaf(a[i], bb[jj], acc[i][jj]);
        }
        if (it + 1 < nk) {
            const int sn = st ^ 1;
            As[sn][aCg * 4 + 0][aRow] = va.x; As[sn][aCg * 4 + 1][aRow] = va.y;
            As[sn][aCg * 4 + 2][aRow] = va.z; As[sn][aCg * 4 + 3][aRow] = va.w;
            Ws[sn][wCg * 4 + 0][wRow] = vw.x; Ws[sn][wCg * 4 + 1][wRow] = vw.y;
            Ws[sn][wCg * 4 + 2][wRow] = vw.z; Ws[sn][wCg * 4 + 3][wRow] = vw.w;
        }
        __syncthreads();
    }

    float* Cp = C + (size_t)blockIdx.y * B * N;
#pragma unroll
    for (int i = 0; i < 4; i++) {
        float4 v = make_float4(acc[i][0], acc[i][1], acc[i][2], acc[i][3]);
        *reinterpret_cast<float4*>(&Cp[(size_t)(tr * 4 + i) * N + nblk + tc * 4]) = v;
    }
}

// ---------------- small full-K GEMM [64,1024]x[1024,1024]^T with fused epilogues ----------------
// Tile 64x16, 64 blocks, 256 threads, microtile 1x4.
// mode 0: qin = 0.5*(h + acc + bias)   mode 1: qf = acc + bias
__global__ __launch_bounds__(256)
void gemm_small(const float* __restrict__ A, const float* __restrict__ W,
                const float* __restrict__ bias, const float* __restrict__ hN,
                float* __restrict__ out, int mode)
{
    __shared__ __align__(16) float As[2][16][68];
    __shared__ __align__(16) float Ws[2][16][20];

    const int tx = threadIdx.x;
    const int tr = tx >> 2;       // 0..63 row
    const int tc = tx & 3;        // cols tc*4..+3
    const int n0 = blockIdx.x * 16;

    const int aRow = tx & 63, aCg = tx >> 6;
    const int wRow = tx >> 2, wCg = tx & 3;   // tx<64: 16 rows x 4 kg
    const bool wAct = (tx < 64);

    const float* Aptr = A + (size_t)aRow * H + aCg * 4;
    const float* Wptr = W + (size_t)(n0 + wRow) * H + wCg * 4;

    float acc[4] = {0.f, 0.f, 0.f, 0.f};

    {
        float4 va = *reinterpret_cast<const float4*>(Aptr);
        As[0][aCg * 4 + 0][aRow] = va.x; As[0][aCg * 4 + 1][aRow] = va.y;
        As[0][aCg * 4 + 2][aRow] = va.z; As[0][aCg * 4 + 3][aRow] = va.w;
        if (wAct) {
            float4 vw = *reinterpret_cast<const float4*>(Wptr);
            Ws[0][wCg * 4 + 0][wRow] = vw.x; Ws[0][wCg * 4 + 1][wRow] = vw.y;
            Ws[0][wCg * 4 + 2][wRow] = vw.z; Ws[0][wCg * 4 + 3][wRow] = vw.w;
        }
    }
    __syncthreads();

    const int nk = H / 16;   // 64
    for (int it = 0; it < nk; it++) {
        const int st = it & 1;
        float4 va, vw;
        if (it + 1 < nk) {
            va = *reinterpret_cast<const float4*>(Aptr + (it + 1) * 16);
            if (wAct) vw = *reinterpret_cast<const float4*>(Wptr + (it + 1) * 16);
        }
#pragma unroll
        for (int kk = 0; kk < 16; kk++) {
            float a = As[st][kk][tr];
            float4 b4 = *reinterpret_cast<const float4*>(&Ws[st][kk][tc * 4]);
            acc[0] = fmaf(a, b4.x, acc[0]);
            acc[1] = fmaf(a, b4.y, acc[1]);
            acc[2] = fmaf(a, b4.z, acc[2]);
            acc[3] = fmaf(a, b4.w, acc[3]);
        }
        if (it + 1 < nk) {
            const int sn = st ^ 1;
            As[sn][aCg * 4 + 0][aRow] = va.x; As[sn][aCg * 4 + 1][aRow] = va.y;
            As[sn][aCg * 4 + 2][aRow] = va.z; As[sn][aCg * 4 + 3][aRow] = va.w;
            if (wAct) {
                Ws[sn][wCg * 4 + 0][wRow] = vw.x; Ws[sn][wCg * 4 + 1][wRow] = vw.y;
                Ws[sn][wCg * 4 + 2][wRow] = vw.z; Ws[sn][wCg * 4 + 3][wRow] = vw.w;
            }
        }
        __syncthreads();
    }

    const int n = n0 + tc * 4;
    float4 bv = *reinterpret_cast<const float4*>(&bias[n]);
    float4 r;
    if (mode == 0) {
        float4 hv = *reinterpret_cast<const float4*>(&hN[(size_t)tr * H + n]);
        r.x = 0.5f * (hv.x + acc[0] + bv.x);
        r.y = 0.5f * (hv.y + acc[1] + bv.y);
        r.z = 0.5f * (hv.z + acc[2] + bv.z);
        r.w = 0.5f * (hv.w + acc[3] + bv.w);
    } else {
        r.x = acc[0] + bv.x; r.y = acc[1] + bv.y;
        r.z = acc[2] + bv.z; r.w = acc[3] + bv.w;
    }
    *reinterpret_cast<float4*>(&out[(size_t)tr * H + n]) = r;
}

// ---------------- fused qkv-finalize + attention ----------------
__global__ __launch_bounds__(256) void qkv_attention(const float* __restrict__ ain_b, int t) {
    int b = blockIdx.x;
    __shared__ __align__(16) float sq[H];
    __shared__ float sc[NH][32];

    for (int j = threadIdx.x; j < K3H; j += 256) {
        float v = ain_b[j];
#pragma unroll
        for (int s = 0; s < KS_QKV; s++)
            v += d_qkvp[(size_t)s * B * K3H + (size_t)b * K3H + j];
        if (j < 1024)       sq[j] = v;
        else if (j < 2048)  d_Kc[((size_t)t * B + b) * H + (j - 1024)] = v;
        else                d_Vc[((size_t)t * B + b) * H + (j - 2048)] = v;
    }
    __syncthreads();

    int w = threadIdx.x >> 5;
    int l = threadIdx.x & 31;
    const float scale = 0.08838834764831845f;

    float4 q4 = *reinterpret_cast<const float4*>(&sq[w * HD + l * 4]);
    for (int s = 0; s <= t; s++) {
        float4 k4 = *reinterpret_cast<const float4*>(&d_Kc[((size_t)s * B + b) * H + w * HD + l * 4]);
        float p = q4.x * k4.x + q4.y * k4.y + q4.z * k4.z + q4.w * k4.w;
#pragma unroll
        for (int off = 16; off; off >>= 1) p += __shfl_xor_sync(0xffffffffu, p, off);
        if (l == 0) sc[w][s] = p * scale;
    }
    __syncwarp();
    float val = (l <= t) ? sc[w][l] : -3.0e38f;
    float mx = val;
#pragma unroll
    for (int off = 16; off; off >>= 1) mx = fmaxf(mx, __shfl_xor_sync(0xffffffffu, mx, off));
    float e = (l <= t) ? expf(val - mx) : 0.f;
    float se = e;
#pragma unroll
    for (int off = 16; off; off >>= 1) se += __shfl_xor_sync(0xffffffffu, se, off);
    float inv = 1.f / se;

    float cx0 = 0.f, cx1 = 0.f, cx2 = 0.f, cx3 = 0.f;
    for (int s = 0; s <= t; s++) {
        float a = __shfl_sync(0xffffffffu, e, s) * inv;
        float4 v4 = *reinterpret_cast<const float4*>(&d_Vc[((size_t)s * B + b) * H + w * HD + l * 4]);
        cx0 = fmaf(a, v4.x, cx0); cx1 = fmaf(a, v4.y, cx1);
        cx2 = fmaf(a, v4.z, cx2); cx3 = fmaf(a, v4.w, cx3);
    }
    float4 o4 = make_float4(cx0, cx1, cx2, cx3);
    *reinterpret_cast<float4*>(&d_ctx[(size_t)b * H + w * HD + l * 4]) = o4;
}

// ---------------- logits + top3 ----------------
__global__ __launch_bounds__(256)
void logits_kernel(const float* __restrict__ enc, float* __restrict__ out, int t) {
    int b = blockIdx.x, ch = blockIdx.y;
    __shared__ __align__(16) float q[H];
    for (int k = threadIdx.x; k < H; k += 256)
        q[k] = d_qf[(size_t)b * H + k];
    __syncthreads();
    int w = threadIdx.x >> 5, l = threadIdx.x & 31;
    for (int ni = 0; ni < 16; ni++) {
        int n = ch * 128 + w * 16 + ni;
        const float4* e4 = reinterpret_cast<const float4*>(&enc[((size_t)b * NE + n) * H]);
        float acc = 0.f;
#pragma unroll
        for (int r = 0; r < 8; r++) {
            float4 ev = e4[l + r * 32];
            float4 qv = *reinterpret_cast<const float4*>(&q[(l + r * 32) * 4]);
            acc += ev.x * qv.x + ev.y * qv.y + ev.z * qv.z + ev.w * qv.w;
        }
#pragma unroll
        for (int off = 16; off; off >>= 1) acc += __shfl_xor_sync(0xffffffffu, acc, off);
        if (l == 0) out[(size_t)t * B * NE + (size_t)b * NE + n] = acc;
    }
}

__global__ __launch_bounds__(128)
void top3_kernel(const float* __restrict__ enc, float* __restrict__ out, int t, int out_size) {
    int b = blockIdx.x;
    __shared__ float s[NE];
    __shared__ int si[3];
    const float* lg = out + (size_t)t * B * NE + (size_t)b * NE;
    for (int n = threadIdx.x; n < NE; n += 128) s[n] = lg[n];
    __syncthreads();
    if (threadIdx.x == 0) {
        float v0 = -3.0e38f, v1 = -3.0e38f, v2 = -3.0e38f;
        int i0 = 0, i1 = 0, i2 = 0;
        for (int n = 0; n < NE; n++) {
            float v = s[n];
            if (v > v0)      { v2 = v1; i2 = i1; v1 = v0; i1 = i0; v0 = v; i0 = n; }
            else if (v > v1) { v2 = v1; i2 = i1; v1 = v; i1 = n; }
            else if (v > v2) { v2 = v; i2 = n; }
        }
        int a0 = i0, a1 = i1, a2 = i2, tmp;
        if (a0 > a1) { tmp = a0; a0 = a1; a1 = tmp; }
        if (a1 > a2) { tmp = a1; a1 = a2; a2 = tmp; }
        if (a0 > a1) { tmp = a0; a0 = a1; a1 = tmp; }
        si[0] = a0; si[1] = a1; si[2] = a2;
        if (out_size >= LOGITS_TOT + IDX_TOT) {
            float* op = out + (size_t)LOGITS_TOT + (size_t)t * B * 3 + (size_t)b * 3;
            op[0] = (float)a0; op[1] = (float)a1; op[2] = (float)a2;
        }
    }
    __syncthreads();
    for (int r = 0; r < 3; r++) {
        const float4* src = reinterpret_cast<const float4*>(&enc[((size_t)b * NE + si[r]) * H]);
        float4* dst = reinterpret_cast<float4*>(&d_X[(size_t)b * K3H + r * H]);
        for (int k = threadIdx.x; k < 256; k += 128) dst[k] = src[k];
    }
}

// ---------------- launch ----------------
extern "C" void kernel_launch(void* const* d_in, const int* in_sizes, int n_in,
                              void* d_out, int out_size) {
    const float* enc     = (const float*)d_in[0];
    const float* hidden  = (const float*)d_in[1];
    const float* cell    = (const float*)d_in[2];
    const float* init_in = (const float*)d_in[4];
    int base = (in_sizes[5] > 1000) ? 5 : 6;   // skip scalar max_steps if present
    const float* W_ih   = (const float*)d_in[base + 0];
    const float* b_ih   = (const float*)d_in[base + 1];
    const float* W_hh   = (const float*)d_in[base + 2];
    const float* b_hh   = (const float*)d_in[base + 3];
    const float* ain_w  = (const float*)d_in[base + 4];
    const float* ain_b  = (const float*)d_in[base + 5];
    const float* aout_w = (const float*)d_in[base + 6];
    const float* aout_b = (const float*)d_in[base + 7];
    const float* qt_w   = (const float*)d_in[base + 8];
    const float* qt_b   = (const float*)d_in[base + 9];
    float* out = (float*)d_out;

    float *pH0, *pQkv, *pCtx, *pQin, *pQf;
    cudaGetSymbolAddress((void**)&pH0,  d_hbuf);
    cudaGetSymbolAddress((void**)&pQkv, d_qkvp);
    cudaGetSymbolAddress((void**)&pCtx, d_ctx);
    cudaGetSymbolAddress((void**)&pQin, d_qin);
    cudaGetSymbolAddress((void**)&pQf,  d_qf);

    init_wcat<<<65536, 256>>>(W_ih, W_hh);
    init_state<<<1024, 256>>>(hidden, cell, init_in, b_ih, b_hh);

    for (int t = 0; t < SQ; t++) {
        float* hin  = pH0 + (size_t)(t & 1) * B * H;
        float* hout = pH0 + (size_t)((t + 1) & 1) * B * H;
        // gates GEMM + fused LSTM (full K, 128 blocks)
        gates_lstm<<<128, 256>>>(hin, hout);
        // fused QKV: [64,3072] = h @ ain_w^T, K-split 4 -> 192 blocks
        gemm64<<<dim3(48, KS_QKV), 256>>>(hout, H, ain_w, H, K3H, pQkv, H / KS_QKV);
        qkv_attention<<<64, 256>>>(ain_b, t);
        // attn_out GEMM + fused qin epilogue
        gemm_small<<<64, 256>>>(pCtx, aout_w, aout_b, hout, pQin, 0);
        // query GEMM + bias epilogue
        gemm_small<<<64, 256>>>(pQin, qt_w, qt_b, (const float*)0, pQf, 1);
        logits_kernel<<<dim3(64, 4), 256>>>(enc, out, t);
        top3_kernel<<<64, 128>>>(enc, out, t, out_size);
    }
}

// round 5
// speedup vs baseline: 2.2031x; 2.2031x over previous
#include <cuda_runtime.h>
#include <math.h>

#define B    64
#define H    1024
#define NH   8
#define HD   128
#define SQ   24
#define NE   512
#define K3H  3072
#define H4   4096

#define LOGITS_TOT (SQ*B*NE)   // 786432
#define IDX_TOT    (SQ*B*3)    // 4608

#define KS_GATES 16
#define KS_QKV   16
#define KS_SMALL 32

// ---------------- persistent device scratch (no allocations allowed) ----------------
__device__ float d_Wcat[(size_t)H4 * H4];     // [4096][4096] = W_ih | W_hh packed
__device__ float d_Xcat[(size_t)B * H4];      // [64][4096]  = x(3072) | h(1024)
__device__ float d_c[(size_t)B * H];
__device__ float d_gatesp[KS_GATES * (size_t)B * H4];
__device__ float d_qkvp[KS_QKV * (size_t)B * K3H];
__device__ float d_Kc[(size_t)SQ * B * H];
__device__ float d_Vc[(size_t)SQ * B * H];
__device__ float d_ctx[(size_t)B * H];
__device__ float d_aop[KS_SMALL * (size_t)B * H];
__device__ float d_qin[(size_t)B * H];
__device__ float d_qp[KS_SMALL * (size_t)B * H];

// ---------------- init kernels ----------------
__global__ void init_wcat(const float* __restrict__ W_ih, const float* __restrict__ W_hh) {
    size_t id = (size_t)blockIdx.x * 256 + threadIdx.x;   // 16.7M elems
    int j = (int)(id >> 12);
    int k = (int)(id & 4095);
    d_Wcat[id] = (k < K3H) ? W_ih[(size_t)j * K3H + k]
                           : W_hh[(size_t)j * H + (k - K3H)];
}

__global__ void init_state(const float* __restrict__ hidden,
                           const float* __restrict__ cell,
                           const float* __restrict__ init_in) {
    int id = blockIdx.x * 256 + threadIdx.x;              // B*H4 = 262144
    int b = id >> 12;
    int k = id & 4095;
    if (k < K3H) {
        d_Xcat[id] = init_in[(size_t)b * K3H + k];
    } else {
        d_Xcat[id] = hidden[(size_t)b * H + (k - K3H)];
        d_c[(size_t)b * H + (k - K3H)] = cell[(size_t)b * H + (k - K3H)];
    }
}

// ---------------- fp32 GEMM: C_part[ky][64][N] = A[64, kslice] * W[N, kslice]^T ----------------
// M=64 fixed. Block tile 64x256, 128 threads, 8x16 microtile (high register reuse:
// 96B smem -> 128 FMA per thread per k, so FMA issue binds, not the LDS crossbar).
// n-columns of a thread are strided (q*64 + tn*4) so b-loads are conflict-free.
// W row-major with row stride == K. Deterministic K-split via blockIdx.y partials.
__global__ __launch_bounds__(128)
void gemm64(const float* __restrict__ A, int lda,
            const float* __restrict__ W, int K, int N,
            float* __restrict__ C, int kper)
{
    __shared__ __align__(16) float As[2][16][72];
    __shared__ __align__(16) float Ws[2][16][260];

    const int tx = threadIdx.x;
    const int tm = tx >> 4;        // 0..7  -> rows tm*8 .. +7
    const int tn = tx & 15;        // 0..15 -> cols q*64 + tn*4 .. +3 (q=0..3)
    const int nblk = blockIdx.x * 256;
    const int k0 = blockIdx.y * kper;

    // loader indices
    const int ldRow = tx >> 2;     // A: 0..31 (+i*32), W: 0..31 (+i*32)
    const int ldKg  = tx & 3;      // k-group of 4 floats

    const float* Aptr = A + (size_t)ldRow * lda + k0 + ldKg * 4;
    const float* Wptr = W + (size_t)(nblk + ldRow) * K + k0 + ldKg * 4;

    float acc[8][16];
#pragma unroll
    for (int i = 0; i < 8; i++)
#pragma unroll
        for (int j = 0; j < 16; j++) acc[i][j] = 0.f;

    const int nk = kper / 16;

    // prologue: fill stage 0
    {
#pragma unroll
        for (int i = 0; i < 2; i++) {
            float4 v = *reinterpret_cast<const float4*>(Aptr + (size_t)i * 32 * lda);
            int row = ldRow + i * 32;
            As[0][ldKg * 4 + 0][row] = v.x; As[0][ldKg * 4 + 1][row] = v.y;
            As[0][ldKg * 4 + 2][row] = v.z; As[0][ldKg * 4 + 3][row] = v.w;
        }
#pragma unroll
        for (int i = 0; i < 8; i++) {
            float4 v = *reinterpret_cast<const float4*>(Wptr + (size_t)i * 32 * K);
            int row = ldRow + i * 32;
            Ws[0][ldKg * 4 + 0][row] = v.x; Ws[0][ldKg * 4 + 1][row] = v.y;
            Ws[0][ldKg * 4 + 2][row] = v.z; Ws[0][ldKg * 4 + 3][row] = v.w;
        }
    }
    __syncthreads();

    for (int it = 0; it < nk; it++) {
        const int st = it & 1;
        float4 va[2], vw[8];
        if (it + 1 < nk) {
            const int koff = (it + 1) * 16;
#pragma unroll
            for (int i = 0; i < 2; i++)
                va[i] = *reinterpret_cast<const float4*>(Aptr + (size_t)i * 32 * lda + koff);
#pragma unroll
            for (int i = 0; i < 8; i++)
                vw[i] = *reinterpret_cast<const float4*>(Wptr + (size_t)i * 32 * K + koff);
        }
#pragma unroll
        for (int kk = 0; kk < 16; kk++) {
            float a[8], bb[16];
            *reinterpret_cast<float4*>(&a[0]) = *reinterpret_cast<const float4*>(&As[st][kk][tm * 8]);
            *reinterpret_cast<float4*>(&a[4]) = *reinterpret_cast<const float4*>(&As[st][kk][tm * 8 + 4]);
#pragma unroll
            for (int q = 0; q < 4; q++)
                *reinterpret_cast<float4*>(&bb[q * 4]) =
                    *reinterpret_cast<const float4*>(&Ws[st][kk][q * 64 + tn * 4]);
#pragma unroll
            for (int i = 0; i < 8; i++)
#pragma unroll
                for (int j = 0; j < 16; j++)
                    acc[i][j] = fmaf(a[i], bb[j], acc[i][j]);
        }
        if (it + 1 < nk) {
            const int sn = st ^ 1;
#pragma unroll
            for (int i = 0; i < 2; i++) {
                int row = ldRow + i * 32;
                As[sn][ldKg * 4 + 0][row] = va[i].x; As[sn][ldKg * 4 + 1][row] = va[i].y;
                As[sn][ldKg * 4 + 2][row] = va[i].z; As[sn][ldKg * 4 + 3][row] = va[i].w;
            }
#pragma unroll
            for (int i = 0; i < 8; i++) {
                int row = ldRow + i * 32;
                Ws[sn][ldKg * 4 + 0][row] = vw[i].x; Ws[sn][ldKg * 4 + 1][row] = vw[i].y;
                Ws[sn][ldKg * 4 + 2][row] = vw[i].z; Ws[sn][ldKg * 4 + 3][row] = vw[i].w;
            }
        }
        __syncthreads();
    }

    float* Cp = C + (size_t)blockIdx.y * B * N;
#pragma unroll
    for (int i = 0; i < 8; i++) {
        const size_t rbase = (size_t)(tm * 8 + i) * N + nblk;
#pragma unroll
        for (int q = 0; q < 4; q++) {
            float4 v = make_float4(acc[i][q * 4 + 0], acc[i][q * 4 + 1],
                                   acc[i][q * 4 + 2], acc[i][q * 4 + 3]);
            *reinterpret_cast<float4*>(&Cp[rbase + q * 64 + tn * 4]) = v;
        }
    }
}

// ---------------- pointwise / small kernels ----------------
__device__ __forceinline__ float sigmoidf_(float x) { return 1.f / (1.f + expf(-x)); }

__global__ void lstm_update(const float* __restrict__ b_ih, const float* __restrict__ b_hh) {
    int id = blockIdx.x * blockDim.x + threadIdx.x;  // B*H
    int b = id >> 10, j = id & 1023;
    size_t base = (size_t)b * H4;
    float gi = b_ih[j]        + b_hh[j];
    float gf = b_ih[1024 + j] + b_hh[1024 + j];
    float gg = b_ih[2048 + j] + b_hh[2048 + j];
    float go = b_ih[3072 + j] + b_hh[3072 + j];
#pragma unroll
    for (int s = 0; s < KS_GATES; s++) {
        const float* g = d_gatesp + (size_t)s * B * H4 + base;
        gi += g[j]; gf += g[1024 + j]; gg += g[2048 + j]; go += g[3072 + j];
    }
    float c = sigmoidf_(gf) * d_c[(size_t)b * H + j] + sigmoidf_(gi) * tanhf(gg);
    d_c[(size_t)b * H + j] = c;
    d_Xcat[base + K3H + j] = sigmoidf_(go) * tanhf(c);
}

// fused: sum qkv partials + bias, scatter K/V to cache, keep q in smem, run attention
__global__ __launch_bounds__(256) void qkv_attention(const float* __restrict__ ain_b, int t) {
    int b = blockIdx.x;
    __shared__ __align__(16) float sq[H];
    __shared__ float sc[NH][32];

    for (int j = threadIdx.x; j < K3H; j += 256) {
        float v = ain_b[j];
#pragma unroll
        for (int s = 0; s < KS_QKV; s++)
            v += d_qkvp[(size_t)s * B * K3H + (size_t)b * K3H + j];
        if (j < 1024)       sq[j] = v;
        else if (j < 2048)  d_Kc[((size_t)t * B + b) * H + (j - 1024)] = v;
        else                d_Vc[((size_t)t * B + b) * H + (j - 2048)] = v;
    }
    __syncthreads();

    int w = threadIdx.x >> 5;
    int l = threadIdx.x & 31;
    const float scale = 0.08838834764831845f;  // 1/sqrt(128)

    float4 q4 = *reinterpret_cast<const float4*>(&sq[w * HD + l * 4]);
    for (int s = 0; s <= t; s++) {
        float4 k4 = *reinterpret_cast<const float4*>(&d_Kc[((size_t)s * B + b) * H + w * HD + l * 4]);
        float p = q4.x * k4.x + q4.y * k4.y + q4.z * k4.z + q4.w * k4.w;
#pragma unroll
        for (int off = 16; off; off >>= 1) p += __shfl_xor_sync(0xffffffffu, p, off);
        if (l == 0) sc[w][s] = p * scale;
    }
    __syncwarp();
    float val = (l <= t) ? sc[w][l] : -3.0e38f;
    float mx = val;
#pragma unroll
    for (int off = 16; off; off >>= 1) mx = fmaxf(mx, __shfl_xor_sync(0xffffffffu, mx, off));
    float e = (l <= t) ? expf(val - mx) : 0.f;
    float se = e;
#pragma unroll
    for (int off = 16; off; off >>= 1) se += __shfl_xor_sync(0xffffffffu, se, off);
    float inv = 1.f / se;

    float cx0 = 0.f, cx1 = 0.f, cx2 = 0.f, cx3 = 0.f;
    for (int s = 0; s <= t; s++) {
        float a = __shfl_sync(0xffffffffu, e, s) * inv;
        float4 v4 = *reinterpret_cast<const float4*>(&d_Vc[((size_t)s * B + b) * H + w * HD + l * 4]);
        cx0 = fmaf(a, v4.x, cx0); cx1 = fmaf(a, v4.y, cx1);
        cx2 = fmaf(a, v4.z, cx2); cx3 = fmaf(a, v4.w, cx3);
    }
    float4 o4 = make_float4(cx0, cx1, cx2, cx3);
    *reinterpret_cast<float4*>(&d_ctx[(size_t)b * H + w * HD + l * 4]) = o4;
}

__global__ void make_qin(const float* __restrict__ aout_b) {
    int id = blockIdx.x * blockDim.x + threadIdx.x;  // B*H
    int k = id & 1023;
    float ao = aout_b[k];
#pragma unroll
    for (int s = 0; s < KS_SMALL; s++) ao += d_aop[(size_t)s * B * H + id];
    d_qin[id] = 0.5f * (d_Xcat[(size_t)(id >> 10) * H4 + K3H + k] + ao);
}

__global__ __launch_bounds__(256)
void logits_kernel(const float* __restrict__ enc, const float* __restrict__ qt_b,
                   float* __restrict__ out, int t) {
    int b = blockIdx.x, ch = blockIdx.y;
    __shared__ __align__(16) float q[H];
    for (int k = threadIdx.x; k < H; k += 256) {
        float v = qt_b[k];
#pragma unroll
        for (int s = 0; s < KS_SMALL; s++) v += d_qp[(size_t)s * B * H + (size_t)b * H + k];
        q[k] = v;
    }
    __syncthreads();
    int w = threadIdx.x >> 5, l = threadIdx.x & 31;
    for (int ni = 0; ni < 16; ni++) {
        int n = ch * 128 + w * 16 + ni;
        const float4* e4 = reinterpret_cast<const float4*>(&enc[((size_t)b * NE + n) * H]);
        float acc = 0.f;
#pragma unroll
        for (int r = 0; r < 8; r++) {
            float4 ev = e4[l + r * 32];
            float4 qv = *reinterpret_cast<const float4*>(&q[(l + r * 32) * 4]);
            acc += ev.x * qv.x + ev.y * qv.y + ev.z * qv.z + ev.w * qv.w;
        }
#pragma unroll
        for (int off = 16; off; off >>= 1) acc += __shfl_xor_sync(0xffffffffu, acc, off);
        if (l == 0) out[(size_t)t * B * NE + (size_t)b * NE + n] = acc;
    }
}

__global__ __launch_bounds__(128)
void top3_kernel(const float* __restrict__ enc, float* __restrict__ out, int t, int out_size) {
    int b = blockIdx.x;
    __shared__ float s[NE];
    __shared__ int si[3];
    const float* lg = out + (size_t)t * B * NE + (size_t)b * NE;
    for (int n = threadIdx.x; n < NE; n += 128) s[n] = lg[n];
    __syncthreads();
    if (threadIdx.x == 0) {
        float v0 = -3.0e38f, v1 = -3.0e38f, v2 = -3.0e38f;
        int i0 = 0, i1 = 0, i2 = 0;
        for (int n = 0; n < NE; n++) {
            float v = s[n];
            if (v > v0)      { v2 = v1; i2 = i1; v1 = v0; i1 = i0; v0 = v; i0 = n; }
            else if (v > v1) { v2 = v1; i2 = i1; v1 = v; i1 = n; }
            else if (v > v2) { v2 = v; i2 = n; }
        }
        int a0 = i0, a1 = i1, a2 = i2, tmp;
        if (a0 > a1) { tmp = a0; a0 = a1; a1 = tmp; }
        if (a1 > a2) { tmp = a1; a1 = a2; a2 = tmp; }
        if (a0 > a1) { tmp = a0; a0 = a1; a1 = tmp; }
        si[0] = a0; si[1] = a1; si[2] = a2;
        if (out_size >= LOGITS_TOT + IDX_TOT) {
            float* op = out + (size_t)LOGITS_TOT + (size_t)t * B * 3 + (size_t)b * 3;
            op[0] = (float)a0; op[1] = (float)a1; op[2] = (float)a2;
        }
    }
    __syncthreads();
    for (int r = 0; r < 3; r++) {
        const float4* src = reinterpret_cast<const float4*>(&enc[((size_t)b * NE + si[r]) * H]);
        float4* dst = reinterpret_cast<float4*>(&d_Xcat[(size_t)b * H4 + r * H]);
        for (int k = threadIdx.x; k < 256; k += 128) dst[k] = src[k];
    }
}

// ---------------- launch ----------------
extern "C" void kernel_launch(void* const* d_in, const int* in_sizes, int n_in,
                              void* d_out, int out_size) {
    const float* enc     = (const float*)d_in[0];
    const float* hidden  = (const float*)d_in[1];
    const float* cell    = (const float*)d_in[2];
    const float* init_in = (const float*)d_in[4];
    int base = (in_sizes[5] > 1000) ? 5 : 6;   // skip scalar max_steps if present
    const float* W_ih   = (const float*)d_in[base + 0];
    const float* b_ih   = (const float*)d_in[base + 1];
    const float* W_hh   = (const float*)d_in[base + 2];
    const float* b_hh   = (const float*)d_in[base + 3];
    const float* ain_w  = (const float*)d_in[base + 4];
    const float* ain_b  = (const float*)d_in[base + 5];
    const float* aout_w = (const float*)d_in[base + 6];
    const float* aout_b = (const float*)d_in[base + 7];
    const float* qt_w   = (const float*)d_in[base + 8];
    const float* qt_b   = (const float*)d_in[base + 9];
    float* out = (float*)d_out;

    float *pW, *pX, *pGates, *pQkv, *pCtx, *pAop, *pQin, *pQp;
    cudaGetSymbolAddress((void**)&pW,    d_Wcat);
    cudaGetSymbolAddress((void**)&pX,    d_Xcat);
    cudaGetSymbolAddress((void**)&pGates,d_gatesp);
    cudaGetSymbolAddress((void**)&pQkv,  d_qkvp);
    cudaGetSymbolAddress((void**)&pCtx,  d_ctx);
    cudaGetSymbolAddress((void**)&pAop,  d_aop);
    cudaGetSymbolAddress((void**)&pQin,  d_qin);
    cudaGetSymbolAddress((void**)&pQp,   d_qp);

    init_wcat<<<65536, 256>>>(W_ih, W_hh);
    init_state<<<1024, 256>>>(hidden, cell, init_in);

    for (int t = 0; t < SQ; t++) {
        // LSTM gates: [64,4096] = Xcat @ Wcat^T; 16 n-blocks x KS 16 -> 256 CTAs, kslice 256
        gemm64<<<dim3(16, KS_GATES), 128>>>(pX, H4, pW, H4, H4, pGates, H4 / KS_GATES);
        lstm_update<<<256, 256>>>(b_ih, b_hh);
        // QKV: [64,3072] = h @ ain_w^T; 12 x 16 -> 192 CTAs, kslice 64
        gemm64<<<dim3(12, KS_QKV), 128>>>(pX + K3H, H4, ain_w, H, K3H, pQkv, H / KS_QKV);
        qkv_attention<<<64, 256>>>(ain_b, t);
        // attn_out: [64,1024] = ctx @ aout_w^T; 4 x 32 -> 128 CTAs, kslice 32
        gemm64<<<dim3(4, KS_SMALL), 128>>>(pCtx, H, aout_w, H, H, pAop, H / KS_SMALL);
        make_qin<<<256, 256>>>(aout_b);
        // query: [64,1024] = qin @ qt_w^T; 4 x 32 -> 128 CTAs, kslice 32
        gemm64<<<dim3(4, KS_SMALL), 128>>>(pQin, H, qt_w, H, H, pQp, H / KS_SMALL);
        logits_kernel<<<dim3(64, 4), 256>>>(enc, qt_b, out, t);
        top3_kernel<<<64, 128>>>(enc, out, t, out_size);
    }
}